// round 11
// baseline (speedup 1.0000x reference)
#include <cuda_runtime.h>
#include <cuda_bf16.h>
#include <cstdint>

#define LSEQ 64
#define HDIM 128
#define PB   136         // bf16 smem pitch: 272B rows -> ldmatrix-compatible
#define SPITCH 65        // scores pitch
#define WPP  24          // pre_mm Wp smem pitch (bf16): 48B, 16B-multiple
#define WCP  40          // pre_mm Wc smem pitch (bf16): 80B, 16B-multiple

// Bias cross terms (fp32) and bf16 bilinear form
struct __align__(16) Pre { float u[HDIM]; float v[HDIM]; float s0; };
__device__ Pre g_pre;
__device__ __nv_bfloat16 g_Mb[HDIM * HDIM];     // M[e][d] bf16, row-major

// ---------------------------------------------------------------------------
// PTX helpers
// ---------------------------------------------------------------------------
__device__ __forceinline__ uint32_t cvta_s(const void* p) {
    return (uint32_t)__cvta_generic_to_shared(p);
}
__device__ __forceinline__ uint32_t pack_bf16x2(float lo, float hi) {
    uint32_t r;
    asm("cvt.rn.bf16x2.f32 %0, %1, %2;" : "=r"(r) : "f"(hi), "f"(lo));
    return r;
}
__device__ __forceinline__ void ldsm_x4(uint32_t* r, uint32_t addr) {
    asm volatile("ldmatrix.sync.aligned.m8n8.x4.shared.b16 {%0,%1,%2,%3}, [%4];\n"
        : "=r"(r[0]), "=r"(r[1]), "=r"(r[2]), "=r"(r[3]) : "r"(addr));
}
__device__ __forceinline__ void ldsm_x4_t(uint32_t* r, uint32_t addr) {
    asm volatile("ldmatrix.sync.aligned.m8n8.x4.trans.shared.b16 {%0,%1,%2,%3}, [%4];\n"
        : "=r"(r[0]), "=r"(r[1]), "=r"(r[2]), "=r"(r[3]) : "r"(addr));
}
__device__ __forceinline__ void ldsm_x2_t(uint32_t* r, uint32_t addr) {
    asm volatile("ldmatrix.sync.aligned.m8n8.x2.trans.shared.b16 {%0,%1}, [%2];\n"
        : "=r"(r[0]), "=r"(r[1]) : "r"(addr));
}
__device__ __forceinline__ void mma_bf16(float* c, const uint32_t* a, const uint32_t* b) {
    asm volatile(
        "mma.sync.aligned.m16n8k16.row.col.f32.bf16.bf16.f32 "
        "{%0,%1,%2,%3}, {%4,%5,%6,%7}, {%8,%9}, {%0,%1,%2,%3};\n"
        : "+f"(c[0]), "+f"(c[1]), "+f"(c[2]), "+f"(c[3])
        : "r"(a[0]), "r"(a[1]), "r"(a[2]), "r"(a[3]), "r"(b[0]), "r"(b[1]));
}
// FFMA-only exp. Valid for the |x| <~ 1 regime of these scores (no max needed:
// scores are O(0.03); the max subtraction cancels exactly in the final ratio).
__device__ __forceinline__ float fast_exp(float x) {
    float t = x * 1.4426950408889634f;
    int   ki = __float2int_rn(t);
    float f  = t - (float)ki;
    float p =          0.0013333558f;
    p = fmaf(p, f, 0.0096181291f);
    p = fmaf(p, f, 0.0555041087f);
    p = fmaf(p, f, 0.2402265070f);
    p = fmaf(p, f, 0.6931471806f);
    p = fmaf(p, f, 1.0f);
    ki = ki < -126 ? -126 : (ki > 126 ? 126 : ki);
    return p * __int_as_float((127 + ki) << 23);
}

// ---------------------------------------------------------------------------
// pre_mm: M[e][d] = (1/1024) sum_{k<1024} Wp[k][e] * Wc[k][d], via tensor cores.
// Grid 32 = 8 e-tiles (16 rows) x 4 d-tiles (32 cols). 128 threads (4 warps).
// Full-K in-CTA => disjoint bf16 output stores, no atomics, no reduce kernel.
// K streamed in 8 double-buffered chunks of 128 (fp32 LDG -> bf16 STS).
// ---------------------------------------------------------------------------
__global__ void __launch_bounds__(128)
pre_mm(const float* __restrict__ Wp, const float* __restrict__ Wc,
       const float* __restrict__ bp, const float* __restrict__ bc) {
    __shared__ __align__(16) __nv_bfloat16 WpS[2][128][WPP];
    __shared__ __align__(16) __nv_bfloat16 WcS[2][128][WCP];
    const int t = threadIdx.x, w = t >> 5, l = t & 31;
    const int e0 = (int)(blockIdx.x >> 2) * 16;
    const int d0 = (int)(blockIdx.x & 3) * 32;

    float4 rc[8], rp[4];
    const float inv = 1.0f / 1024.0f;

    // chunk 0 -> regs -> smem buf 0
    {
        const int k0 = 0;
        #pragma unroll
        for (int j = 0; j < 8; j++) {
            int i = t + j * 128;
            rc[j] = *(const float4*)&Wc[(size_t)(k0 + (i >> 3)) * HDIM + d0 + (i & 7) * 4];
        }
        #pragma unroll
        for (int j = 0; j < 4; j++) {
            int i = t + j * 128;
            rp[j] = *(const float4*)&Wp[(size_t)(k0 + (i >> 2)) * HDIM + e0 + (i & 3) * 4];
        }
        #pragma unroll
        for (int j = 0; j < 8; j++) {
            int i = t + j * 128;
            uint2 v; v.x = pack_bf16x2(rc[j].x, rc[j].y); v.y = pack_bf16x2(rc[j].z, rc[j].w);
            *(uint2*)&WcS[0][i >> 3][(i & 7) * 4] = v;
        }
        #pragma unroll
        for (int j = 0; j < 4; j++) {
            int i = t + j * 128;
            uint2 v; v.x = pack_bf16x2(rp[j].x, rp[j].y); v.y = pack_bf16x2(rp[j].z, rp[j].w);
            *(uint2*)&WpS[0][i >> 2][(i & 3) * 4] = v;
        }
    }
    __syncthreads();

    float acc[4] = {0.f, 0.f, 0.f, 0.f};
    #pragma unroll 1
    for (int c = 0; c < 8; c++) {
        if (c < 7) {                       // prefetch next chunk to regs
            const int k0 = (c + 1) * 128;
            #pragma unroll
            for (int j = 0; j < 8; j++) {
                int i = t + j * 128;
                rc[j] = *(const float4*)&Wc[(size_t)(k0 + (i >> 3)) * HDIM + d0 + (i & 7) * 4];
            }
            #pragma unroll
            for (int j = 0; j < 4; j++) {
                int i = t + j * 128;
                rp[j] = *(const float4*)&Wp[(size_t)(k0 + (i >> 2)) * HDIM + e0 + (i & 3) * 4];
            }
        }
        // MMA on buffer c&1: 8 k-steps of 16
        {
            const uint32_t baseA = cvta_s(&WpS[c & 1][0][0]);
            const uint32_t baseB = cvta_s(&WcS[c & 1][0][0]);
            #pragma unroll
            for (int ks = 0; ks < 8; ks++) {
                uint32_t ra[4], a[4], b[2];
                ldsm_x4_t(ra, baseA + (uint32_t)(ks * 16 + (l & 15)) * (WPP * 2) + (l >> 4) * 16);
                a[0] = ra[0]; a[1] = ra[2]; a[2] = ra[1]; a[3] = ra[3];  // quadrant swap for A
                ldsm_x2_t(b, baseB + (uint32_t)(ks * 16 + (l & 15)) * (WCP * 2) + w * 16);
                mma_bf16(acc, a, b);
            }
        }
        if (c < 7) {                       // store next chunk to buf (c+1)&1
            const int nb = (c + 1) & 1;
            #pragma unroll
            for (int j = 0; j < 8; j++) {
                int i = t + j * 128;
                uint2 v; v.x = pack_bf16x2(rc[j].x, rc[j].y); v.y = pack_bf16x2(rc[j].z, rc[j].w);
                *(uint2*)&WcS[nb][i >> 3][(i & 7) * 4] = v;
            }
            #pragma unroll
            for (int j = 0; j < 4; j++) {
                int i = t + j * 128;
                uint2 v; v.x = pack_bf16x2(rp[j].x, rp[j].y); v.y = pack_bf16x2(rp[j].z, rp[j].w);
                *(uint2*)&WpS[nb][i >> 2][(i & 3) * 4] = v;
            }
        }
        __syncthreads();
    }

    // store 16x8 warp tile of M (bf16, scaled)
    {
        const int row = l >> 2, col = d0 + w * 8 + 2 * (l & 3);
        *(uint32_t*)&g_Mb[(size_t)(e0 + row) * HDIM + col]     = pack_bf16x2(acc[0] * inv, acc[1] * inv);
        *(uint32_t*)&g_Mb[(size_t)(e0 + row + 8) * HDIM + col] = pack_bf16x2(acc[2] * inv, acc[3] * inv);
    }

    // ---- bias cross terms (zero-valued in this dataset; kept for generality)
    if ((blockIdx.x & 3) == 0) {           // u[e0..e0+16): 8 CTAs
        const int e = e0 + (t >> 3), kl = t & 7;
        float s[4] = {0.f, 0.f, 0.f, 0.f};
        #pragma unroll 1
        for (int k0 = 0; k0 < 1024; k0 += 32) {
            #pragma unroll
            for (int m = 0; m < 4; m++) {
                int k = k0 + kl + 8 * m;
                s[m] += Wp[(size_t)k * HDIM + e] * bc[k];
            }
        }
        float su = (s[0] + s[1]) + (s[2] + s[3]);
        su += __shfl_xor_sync(~0u, su, 4);
        su += __shfl_xor_sync(~0u, su, 2);
        su += __shfl_xor_sync(~0u, su, 1);
        if (kl == 0) g_pre.u[e] = su * inv;
    }
    if ((blockIdx.x >> 2) == 0) {          // v[d0..d0+32): 4 CTAs
        const int d = d0 + (t >> 2), kl = t & 3;
        float s[4] = {0.f, 0.f, 0.f, 0.f};
        #pragma unroll 1
        for (int k0 = 0; k0 < 1024; k0 += 16) {
            #pragma unroll
            for (int m = 0; m < 4; m++) {
                int k = k0 + kl + 4 * m;
                s[m] += Wc[(size_t)k * HDIM + d] * bp[k];
            }
        }
        float sv = (s[0] + s[1]) + (s[2] + s[3]);
        sv += __shfl_xor_sync(~0u, sv, 2);
        sv += __shfl_xor_sync(~0u, sv, 1);
        if (kl == 0) g_pre.v[d] = sv * inv;
    }
    if (blockIdx.x == 0 && t < 32) {       // s0
        float s = 0.f;
        for (int k = t; k < 1024; k += 32) s += bp[k] * bc[k];
        #pragma unroll
        for (int o = 16; o > 0; o >>= 1) s += __shfl_xor_sync(~0u, s, o);
        if (t == 0) g_pre.s0 = s * inv;
    }
}

// ---------------------------------------------------------------------------
// Main fused kernel — one CTA per batch, 512 threads, 2 CTAs/SM (one wave)
// ---------------------------------------------------------------------------
struct SmemMain {
    __nv_bfloat16 Apb[LSEQ][PB];       // pep bf16 [p][e]
    __nv_bfloat16 Cb[LSEQ][PB];        // cdr3 bf16 [c][d]
    char MbS[HDIM * PB * 2];           // Mb bf16 [e][d]; S fp32 overlays after GEMM1
    __nv_bfloat16 PMb[LSEQ][PB];       // pep@M bf16 [p][d]
    float EP[16][HDIM];                // epilogue per-warp partials
    float pu[LSEQ], cv[LSEQ], RS[LSEQ], CS[LSEQ];
    float Z, s0;
};

__global__ void __launch_bounds__(512, 2)
main_kernel(const float* __restrict__ pep, const float* __restrict__ cdr3,
            float* __restrict__ out) {
    extern __shared__ char smem_raw[];
    SmemMain& sm = *(SmemMain*)smem_raw;
    __nv_bfloat16 (*Mb)[PB] = reinterpret_cast<__nv_bfloat16(*)[PB]>(sm.MbS);
    float (*S)[SPITCH]      = reinterpret_cast<float(*)[SPITCH]>(sm.MbS);

    const int t = threadIdx.x;
    const int b = blockIdx.x;
    const int w = t >> 5, l = t & 31;

    // ---- stage inputs (bf16 smem copies) + M ----
    const float* pepG = pep  + (size_t)b * LSEQ * HDIM;
    const float* cdrG = cdr3 + (size_t)b * LSEQ * HDIM;
    const float4* pep4 = (const float4*)pepG;
    const float4* cdr4 = (const float4*)cdrG;
    for (int i = t; i < LSEQ * (HDIM / 4); i += 512) {
        int r = i >> 5, c4 = (i & 31) * 4;
        float4 v = pep4[i];
        *(uint32_t*)&sm.Apb[r][c4]     = pack_bf16x2(v.x, v.y);
        *(uint32_t*)&sm.Apb[r][c4 + 2] = pack_bf16x2(v.z, v.w);
        float4 u = cdr4[i];
        *(uint32_t*)&sm.Cb[r][c4]      = pack_bf16x2(u.x, u.y);
        *(uint32_t*)&sm.Cb[r][c4 + 2]  = pack_bf16x2(u.z, u.w);
    }
    const uint4* Mb4 = (const uint4*)g_Mb;
    for (int i = t; i < HDIM * (HDIM / 8); i += 512) {   // 8 bf16 per uint4
        int r = i >> 4, c8 = (i & 15) * 8;
        *(uint4*)&Mb[r][c8] = Mb4[i];
    }
    if (t == 0) sm.s0 = g_pre.s0;
    __syncthreads();

    // ---- bias projections: 16 warps x 8 tasks, 4 elems/lane + shfl tree ----
    // (zero-valued in this dataset; kept for generality)
    {
        const int e0 = l * 4;
        #pragma unroll
        for (int q = 0; q < 8; q++) {
            const int task = w * 8 + q;      // 0..127
            float4 wv;
            const __nv_bfloat16* rowp;
            if (task < 64) { wv = *(const float4*)&g_pre.u[e0]; rowp = &sm.Apb[task][e0]; }
            else           { wv = *(const float4*)&g_pre.v[e0]; rowp = &sm.Cb[task - 64][e0]; }
            __nv_bfloat162 x0 = *(const __nv_bfloat162*)rowp;
            __nv_bfloat162 x1 = *(const __nv_bfloat162*)(rowp + 2);
            float s = __bfloat162float(x0.x) * wv.x + __bfloat162float(x0.y) * wv.y
                    + __bfloat162float(x1.x) * wv.z + __bfloat162float(x1.y) * wv.w;
            #pragma unroll
            for (int o = 16; o > 0; o >>= 1) s += __shfl_xor_sync(~0u, s, o);
            if (l == 0) {
                if (task < 64) sm.pu[task] = s;
                else           sm.cv[task - 64] = s;
            }
        }
    }

    // ---- GEMM1 (tensor cores): PM = Apb @ Mb,  64x128x128 ----
    {
        const int p0 = (w & 3) * 16, nb = (w >> 2) * 32;
        const uint32_t aA  = cvta_s(&sm.Apb[0][0]) + (uint32_t)(p0 + (l & 15)) * (PB * 2) + (l >> 4) * 16;
        const uint32_t aB1 = cvta_s(&Mb[0][0])     + (uint32_t)(l & 15) * (PB * 2) + nb * 2 + (l >> 4) * 16;
        float acc[4][4] = {};
        #pragma unroll
        for (int ks = 0; ks < 8; ks++) {
            uint32_t a[4], b1[4], b2[4];
            ldsm_x4(a, aA + ks * 32);
            ldsm_x4_t(b1, aB1 + ks * (16 * PB * 2));
            ldsm_x4_t(b2, aB1 + ks * (16 * PB * 2) + 32);
            mma_bf16(acc[0], a, b1);
            mma_bf16(acc[1], a, b1 + 2);
            mma_bf16(acc[2], a, b2);
            mma_bf16(acc[3], a, b2 + 2);
        }
        const int r0 = p0 + (l >> 2), cc = 2 * (l & 3);
        #pragma unroll
        for (int j = 0; j < 4; j++) {
            int n0 = nb + 8 * j;
            *(uint32_t*)&sm.PMb[r0][n0 + cc]     = pack_bf16x2(acc[j][0], acc[j][1]);
            *(uint32_t*)&sm.PMb[r0 + 8][n0 + cc] = pack_bf16x2(acc[j][2], acc[j][3]);
        }
    }
    __syncthreads();   // Mb dead from here; S takes over its storage

    // ---- GEMM2 (tensor cores): S = exp(PMb @ Cb^T + biases), 64x64x128 ----
    {
        const int p0 = (w & 3) * 16, cb = (w >> 2) * 16;
        const uint32_t aA = cvta_s(&sm.PMb[0][0]) + (uint32_t)(p0 + (l & 15)) * (PB * 2) + (l >> 4) * 16;
        const uint32_t aB = cvta_s(&sm.Cb[0][0])
                          + (uint32_t)(cb + (l >> 4) * 8 + (l & 7)) * (PB * 2)
                          + ((l >> 3) & 1) * 16;
        float acc[2][4] = {};
        #pragma unroll
        for (int ks = 0; ks < 8; ks++) {
            uint32_t a[4], bb[4];
            ldsm_x4(a, aA + ks * 32);
            ldsm_x4(bb, aB + ks * 32);
            mma_bf16(acc[0], a, bb);
            mma_bf16(acc[1], a, bb + 2);
        }
        const int r0 = p0 + (l >> 2), cc = 2 * (l & 3);
        const float s0v = sm.s0;
        const float puA = sm.pu[r0], puB = sm.pu[r0 + 8];
        #pragma unroll
        for (int j = 0; j < 2; j++) {
            int c0 = cb + 8 * j + cc;
            float cv0 = sm.cv[c0], cv1 = sm.cv[c0 + 1];
            S[r0][c0]         = fast_exp(acc[j][0] + puA + cv0 + s0v);
            S[r0][c0 + 1]     = fast_exp(acc[j][1] + puA + cv1 + s0v);
            S[r0 + 8][c0]     = fast_exp(acc[j][2] + puB + cv0 + s0v);
            S[r0 + 8][c0 + 1] = fast_exp(acc[j][3] + puB + cv1 + s0v);
        }
    }

    // ---- epilogue prefetch: independent global loads, consumed 2 syncs later
    float4 pv[4], cw4[4];
    #pragma unroll
    for (int r = 0; r < 4; r++) {
        const int row = w * 4 + r;
        pv[r]  = *(const float4*)&pepG[(size_t)row * HDIM + 4 * l];
        cw4[r] = *(const float4*)&cdrG[(size_t)row * HDIM + 4 * l];
    }
    __syncthreads();

    // ---- row/col sums: 16 warps x 8 tasks, lane-parallel + shfl reduce ----
    #pragma unroll
    for (int q = 0; q < 8; q++) {
        const int task = w + q * 16;      // 0..127
        float s;
        if (task < 64) {                  // row sum
            s = S[task][l] + S[task][l + 32];
        } else {                          // col sum (stride 65 -> conflict-free)
            const int c = task - 64;
            s = S[l][c] + S[l + 32][c];
        }
        #pragma unroll
        for (int o = 16; o > 0; o >>= 1) s += __shfl_xor_sync(~0u, s, o);
        if (l == 0) {
            if (task < 64) sm.RS[task] = s;
            else           sm.CS[task - 64] = s;
        }
    }
    __syncthreads();
    if (t < 32) {
        float z = sm.RS[t] + sm.RS[t + 32];
        #pragma unroll
        for (int o = 16; o > 0; o >>= 1) z += __shfl_xor_sync(~0u, z, o);
        if (t == 0) sm.Z = z;
    }
    __syncthreads();

    // ---- epilogue (fp32, prefetched registers) ----
    {
        float a0 = 0.f, a1 = 0.f, a2 = 0.f, a3 = 0.f;
        #pragma unroll
        for (int r = 0; r < 4; r++) {
            const int row = w * 4 + r;
            const float cw = sm.CS[row];
            const float rw = sm.RS[row];
            a0 += pv[r].x * cw + cw4[r].x * rw;
            a1 += pv[r].y * cw + cw4[r].y * rw;
            a2 += pv[r].z * cw + cw4[r].z * rw;
            a3 += pv[r].w * cw + cw4[r].w * rw;
        }
        *(float4*)&sm.EP[w][4 * l] = make_float4(a0, a1, a2, a3);
    }
    __syncthreads();
    if (t < HDIM) {
        float s = 0.f;
        #pragma unroll
        for (int i = 0; i < 16; i++) s += sm.EP[i][t];
        out[(size_t)b * HDIM + t] = s / sm.Z;
    }
}

// ---------------------------------------------------------------------------
extern "C" void kernel_launch(void* const* d_in, const int* in_sizes, int n_in,
                              void* d_out, int out_size) {
    const float* pep = (const float*)d_in[0];
    const float* cdr = (const float*)d_in[1];
    const float* Wc  = (const float*)d_in[2];
    const float* bc  = (const float*)d_in[3];
    const float* Wp  = (const float*)d_in[4];
    const float* bp  = (const float*)d_in[5];
    float* out = (float*)d_out;

    const int B = in_sizes[0] / (LSEQ * HDIM);   // 256

    cudaFuncSetAttribute(main_kernel, cudaFuncAttributeMaxDynamicSharedMemorySize,
                         (int)sizeof(SmemMain));

    pre_mm<<<32, 128>>>(Wp, Wc, bp, bc);
    main_kernel<<<B, 512, sizeof(SmemMain)>>>(pep, cdr, out);
}

// round 13
// speedup vs baseline: 1.2342x; 1.2342x over previous
#include <cuda_runtime.h>
#include <cuda_bf16.h>
#include <cstdint>

#define LSEQ 64
#define HDIM 128
#define PB   136         // bf16 smem pitch: 272B rows -> ldmatrix-compatible
#define SPITCH 65        // scores pitch
#define WPP  24          // pre_mm Wp smem pitch (bf16): 48B rows
#define WCP  40          // pre_mm Wc smem pitch (bf16): 80B rows

// Bias cross terms (fp32) and bf16 bilinear form
struct __align__(16) Pre { float u[HDIM]; float v[HDIM]; float s0; };
__device__ Pre g_pre;
__device__ __nv_bfloat16 g_Mb[HDIM * HDIM];     // M[e][d] bf16, row-major

// ---------------------------------------------------------------------------
// PTX helpers
// ---------------------------------------------------------------------------
__device__ __forceinline__ uint32_t cvta_s(const void* p) {
    return (uint32_t)__cvta_generic_to_shared(p);
}
__device__ __forceinline__ uint32_t pack_bf16x2(float lo, float hi) {
    uint32_t r;
    asm("cvt.rn.bf16x2.f32 %0, %1, %2;" : "=r"(r) : "f"(hi), "f"(lo));
    return r;
}
__device__ __forceinline__ void ldsm_x4(uint32_t* r, uint32_t addr) {
    asm volatile("ldmatrix.sync.aligned.m8n8.x4.shared.b16 {%0,%1,%2,%3}, [%4];\n"
        : "=r"(r[0]), "=r"(r[1]), "=r"(r[2]), "=r"(r[3]) : "r"(addr));
}
__device__ __forceinline__ void ldsm_x4_t(uint32_t* r, uint32_t addr) {
    asm volatile("ldmatrix.sync.aligned.m8n8.x4.trans.shared.b16 {%0,%1,%2,%3}, [%4];\n"
        : "=r"(r[0]), "=r"(r[1]), "=r"(r[2]), "=r"(r[3]) : "r"(addr));
}
__device__ __forceinline__ void ldsm_x2_t(uint32_t* r, uint32_t addr) {
    asm volatile("ldmatrix.sync.aligned.m8n8.x2.trans.shared.b16 {%0,%1}, [%2];\n"
        : "=r"(r[0]), "=r"(r[1]) : "r"(addr));
}
__device__ __forceinline__ void mma_bf16(float* c, const uint32_t* a, const uint32_t* b) {
    asm volatile(
        "mma.sync.aligned.m16n8k16.row.col.f32.bf16.bf16.f32 "
        "{%0,%1,%2,%3}, {%4,%5,%6,%7}, {%8,%9}, {%0,%1,%2,%3};\n"
        : "+f"(c[0]), "+f"(c[1]), "+f"(c[2]), "+f"(c[3])
        : "r"(a[0]), "r"(a[1]), "r"(a[2]), "r"(a[3]), "r"(b[0]), "r"(b[1]));
}
// FFMA-only exp. Valid for the |x| <~ 1 regime of these scores (no max needed:
// scores are O(0.03); the max subtraction cancels exactly in the final ratio).
__device__ __forceinline__ float fast_exp(float x) {
    float t = x * 1.4426950408889634f;
    int   ki = __float2int_rn(t);
    float f  = t - (float)ki;
    float p =          0.0013333558f;
    p = fmaf(p, f, 0.0096181291f);
    p = fmaf(p, f, 0.0555041087f);
    p = fmaf(p, f, 0.2402265070f);
    p = fmaf(p, f, 0.6931471806f);
    p = fmaf(p, f, 1.0f);
    ki = ki < -126 ? -126 : (ki > 126 ? 126 : ki);
    return p * __int_as_float((127 + ki) << 23);
}

// ---------------------------------------------------------------------------
// pre_mm v3: M[e][d] = (1/1024) sum_k Wp[k][e] * Wc[k][d] via tensor cores.
// Grid 40 x 256 threads, STATIC 32KB smem only, no early returns in MMA path:
//   CTAs 0..31:  one 16x32 tile of M; K streamed in 4 chunks of 256 through a
//                single-buffered smem stage; k split across warp halves;
//                deterministic in-smem half reduction; direct bf16 stores.
//   CTAs 32..39: bias cross terms, warp-per-output, lane-parallel k + shfl.
// ---------------------------------------------------------------------------
__global__ void __launch_bounds__(256)
pre_mm(const float* __restrict__ Wp, const float* __restrict__ Wc,
       const float* __restrict__ bp, const float* __restrict__ bc) {
    __shared__ __align__(16) __nv_bfloat16 WpS[256][WPP];   // 12 KB
    __shared__ __align__(16) __nv_bfloat16 WcS[256][WCP];   // 20 KB
    const int t = threadIdx.x, w = t >> 5, l = t & 31;
    const int bx = blockIdx.x;
    const float inv = 1.0f / 1024.0f;

    if (bx >= 32) {       // ---- bias cross terms (zero-valued here; generality)
        const int g = bx - 32;
        #pragma unroll
        for (int j = 0; j < 2; j++) {
            const int e = g * 16 + w * 2 + j;
            float su = 0.f, sv = 0.f;
            #pragma unroll
            for (int i = 0; i < 32; i++) {
                const int k = l + 32 * i;
                su += Wp[(size_t)k * HDIM + e] * bc[k];
                sv += Wc[(size_t)k * HDIM + e] * bp[k];
            }
            #pragma unroll
            for (int o = 16; o > 0; o >>= 1) {
                su += __shfl_xor_sync(~0u, su, o);
                sv += __shfl_xor_sync(~0u, sv, o);
            }
            if (l == 0) { g_pre.u[e] = su * inv; g_pre.v[e] = sv * inv; }
        }
        if (g == 0 && w == 0) {
            float s = 0.f;
            #pragma unroll
            for (int i = 0; i < 32; i++) { const int k = l + 32 * i; s += bp[k] * bc[k]; }
            #pragma unroll
            for (int o = 16; o > 0; o >>= 1) s += __shfl_xor_sync(~0u, s, o);
            if (l == 0) g_pre.s0 = s * inv;
        }
        return;
    }

    const int e0 = (bx >> 2) * 16, d0 = (bx & 3) * 32;
    const int wn = w & 3, wk = w >> 2;
    float acc[4] = {0.f, 0.f, 0.f, 0.f};

    #pragma unroll 1
    for (int c = 0; c < 4; c++) {
        const int k0 = c * 256;
        // stage chunk: fp32 LDG -> bf16 STS (all loads independent)
        #pragma unroll
        for (int j = 0; j < 4; j++) {          // Wp: 256 rows x 16 cols
            int i = t + j * 256, row = i >> 2, col = (i & 3) * 4;
            float4 v = *(const float4*)&Wp[(size_t)(k0 + row) * HDIM + e0 + col];
            uint2 u; u.x = pack_bf16x2(v.x, v.y); u.y = pack_bf16x2(v.z, v.w);
            *(uint2*)&WpS[row][col] = u;
        }
        #pragma unroll
        for (int j = 0; j < 8; j++) {          // Wc: 256 rows x 32 cols
            int i = t + j * 256, row = i >> 3, col = (i & 7) * 4;
            float4 v = *(const float4*)&Wc[(size_t)(k0 + row) * HDIM + d0 + col];
            uint2 u; u.x = pack_bf16x2(v.x, v.y); u.y = pack_bf16x2(v.z, v.w);
            *(uint2*)&WcS[row][col] = u;
        }
        __syncthreads();

        // MMA on chunk: warp-half wk takes k-rows [wk*128, wk*128+128)
        const uint32_t baseA = cvta_s(&WpS[0][0]) + (uint32_t)(l & 15) * (WPP * 2) + (l >> 4) * 16;
        const uint32_t baseB = cvta_s(&WcS[0][0]) + (uint32_t)(l & 15) * (WCP * 2) + wn * 16;
        #pragma unroll
        for (int ks = 0; ks < 8; ks++) {
            const uint32_t k = (uint32_t)(wk * 128 + ks * 16);
            uint32_t ra[4], a[4], b[2];
            ldsm_x4_t(ra, baseA + k * (WPP * 2));
            a[0] = ra[0]; a[1] = ra[2]; a[2] = ra[1]; a[3] = ra[3];   // quadrant swap (A^T)
            ldsm_x2_t(b, baseB + k * (WCP * 2));
            mma_bf16(acc, a, b);
        }
        __syncthreads();   // buffer reused next chunk (or as scratch below)
    }

    // deterministic cross-half reduction via smem scratch, then bf16 store
    float* scratch = (float*)&WpS[0][0];
    if (wk == 1)
        *(float4*)&scratch[(wn * 32 + l) * 4] = make_float4(acc[0], acc[1], acc[2], acc[3]);
    __syncthreads();
    if (wk == 0) {
        float4 o = *(float4*)&scratch[(wn * 32 + l) * 4];
        acc[0] += o.x; acc[1] += o.y; acc[2] += o.z; acc[3] += o.w;
        const int row = l >> 2, col = d0 + wn * 8 + 2 * (l & 3);
        *(uint32_t*)&g_Mb[(size_t)(e0 + row) * HDIM + col]     = pack_bf16x2(acc[0] * inv, acc[1] * inv);
        *(uint32_t*)&g_Mb[(size_t)(e0 + row + 8) * HDIM + col] = pack_bf16x2(acc[2] * inv, acc[3] * inv);
    }
}

// ---------------------------------------------------------------------------
// Main fused kernel — one CTA per batch, 512 threads, 2 CTAs/SM (one wave)
// (byte-identical logic to R11's passing main_kernel)
// ---------------------------------------------------------------------------
struct SmemMain {
    __nv_bfloat16 Apb[LSEQ][PB];       // pep bf16 [p][e]
    __nv_bfloat16 Cb[LSEQ][PB];        // cdr3 bf16 [c][d]
    char MbS[HDIM * PB * 2];           // Mb bf16 [e][d]; S fp32 overlays after GEMM1
    __nv_bfloat16 PMb[LSEQ][PB];       // pep@M bf16 [p][d]
    float EP[16][HDIM];                // epilogue per-warp partials
    float pu[LSEQ], cv[LSEQ], RS[LSEQ], CS[LSEQ];
    float Z, s0;
};

__global__ void __launch_bounds__(512, 2)
main_kernel(const float* __restrict__ pep, const float* __restrict__ cdr3,
            float* __restrict__ out) {
    extern __shared__ char smem_raw[];
    SmemMain& sm = *(SmemMain*)smem_raw;
    __nv_bfloat16 (*Mb)[PB] = reinterpret_cast<__nv_bfloat16(*)[PB]>(sm.MbS);
    float (*S)[SPITCH]      = reinterpret_cast<float(*)[SPITCH]>(sm.MbS);

    const int t = threadIdx.x;
    const int b = blockIdx.x;
    const int w = t >> 5, l = t & 31;

    // ---- stage inputs (bf16 smem copies) + M ----
    const float* pepG = pep  + (size_t)b * LSEQ * HDIM;
    const float* cdrG = cdr3 + (size_t)b * LSEQ * HDIM;
    const float4* pep4 = (const float4*)pepG;
    const float4* cdr4 = (const float4*)cdrG;
    for (int i = t; i < LSEQ * (HDIM / 4); i += 512) {
        int r = i >> 5, c4 = (i & 31) * 4;
        float4 v = pep4[i];
        *(uint32_t*)&sm.Apb[r][c4]     = pack_bf16x2(v.x, v.y);
        *(uint32_t*)&sm.Apb[r][c4 + 2] = pack_bf16x2(v.z, v.w);
        float4 u = cdr4[i];
        *(uint32_t*)&sm.Cb[r][c4]      = pack_bf16x2(u.x, u.y);
        *(uint32_t*)&sm.Cb[r][c4 + 2]  = pack_bf16x2(u.z, u.w);
    }
    const uint4* Mb4 = (const uint4*)g_Mb;
    for (int i = t; i < HDIM * (HDIM / 8); i += 512) {   // 8 bf16 per uint4
        int r = i >> 4, c8 = (i & 15) * 8;
        *(uint4*)&Mb[r][c8] = Mb4[i];
    }
    if (t == 0) sm.s0 = g_pre.s0;
    __syncthreads();

    // ---- bias projections: 16 warps x 8 tasks, 4 elems/lane + shfl tree ----
    {
        const int e0 = l * 4;
        #pragma unroll
        for (int q = 0; q < 8; q++) {
            const int task = w * 8 + q;      // 0..127
            float4 wv;
            const __nv_bfloat16* rowp;
            if (task < 64) { wv = *(const float4*)&g_pre.u[e0]; rowp = &sm.Apb[task][e0]; }
            else           { wv = *(const float4*)&g_pre.v[e0]; rowp = &sm.Cb[task - 64][e0]; }
            __nv_bfloat162 x0 = *(const __nv_bfloat162*)rowp;
            __nv_bfloat162 x1 = *(const __nv_bfloat162*)(rowp + 2);
            float s = __bfloat162float(x0.x) * wv.x + __bfloat162float(x0.y) * wv.y
                    + __bfloat162float(x1.x) * wv.z + __bfloat162float(x1.y) * wv.w;
            #pragma unroll
            for (int o = 16; o > 0; o >>= 1) s += __shfl_xor_sync(~0u, s, o);
            if (l == 0) {
                if (task < 64) sm.pu[task] = s;
                else           sm.cv[task - 64] = s;
            }
        }
    }

    // ---- GEMM1 (tensor cores): PM = Apb @ Mb,  64x128x128 ----
    {
        const int p0 = (w & 3) * 16, nb = (w >> 2) * 32;
        const uint32_t aA  = cvta_s(&sm.Apb[0][0]) + (uint32_t)(p0 + (l & 15)) * (PB * 2) + (l >> 4) * 16;
        const uint32_t aB1 = cvta_s(&Mb[0][0])     + (uint32_t)(l & 15) * (PB * 2) + nb * 2 + (l >> 4) * 16;
        float acc[4][4] = {};
        #pragma unroll
        for (int ks = 0; ks < 8; ks++) {
            uint32_t a[4], b1[4], b2[4];
            ldsm_x4(a, aA + ks * 32);
            ldsm_x4_t(b1, aB1 + ks * (16 * PB * 2));
            ldsm_x4_t(b2, aB1 + ks * (16 * PB * 2) + 32);
            mma_bf16(acc[0], a, b1);
            mma_bf16(acc[1], a, b1 + 2);
            mma_bf16(acc[2], a, b2);
            mma_bf16(acc[3], a, b2 + 2);
        }
        const int r0 = p0 + (l >> 2), cc = 2 * (l & 3);
        #pragma unroll
        for (int j = 0; j < 4; j++) {
            int n0 = nb + 8 * j;
            *(uint32_t*)&sm.PMb[r0][n0 + cc]     = pack_bf16x2(acc[j][0], acc[j][1]);
            *(uint32_t*)&sm.PMb[r0 + 8][n0 + cc] = pack_bf16x2(acc[j][2], acc[j][3]);
        }
    }
    __syncthreads();   // Mb dead from here; S takes over its storage

    // ---- GEMM2 (tensor cores): S = exp(PMb @ Cb^T + biases), 64x64x128 ----
    {
        const int p0 = (w & 3) * 16, cb = (w >> 2) * 16;
        const uint32_t aA = cvta_s(&sm.PMb[0][0]) + (uint32_t)(p0 + (l & 15)) * (PB * 2) + (l >> 4) * 16;
        const uint32_t aB = cvta_s(&sm.Cb[0][0])
                          + (uint32_t)(cb + (l >> 4) * 8 + (l & 7)) * (PB * 2)
                          + ((l >> 3) & 1) * 16;
        float acc[2][4] = {};
        #pragma unroll
        for (int ks = 0; ks < 8; ks++) {
            uint32_t a[4], bb[4];
            ldsm_x4(a, aA + ks * 32);
            ldsm_x4(bb, aB + ks * 32);
            mma_bf16(acc[0], a, bb);
            mma_bf16(acc[1], a, bb + 2);
        }
        const int r0 = p0 + (l >> 2), cc = 2 * (l & 3);
        const float s0v = sm.s0;
        const float puA = sm.pu[r0], puB = sm.pu[r0 + 8];
        #pragma unroll
        for (int j = 0; j < 2; j++) {
            int c0 = cb + 8 * j + cc;
            float cv0 = sm.cv[c0], cv1 = sm.cv[c0 + 1];
            S[r0][c0]         = fast_exp(acc[j][0] + puA + cv0 + s0v);
            S[r0][c0 + 1]     = fast_exp(acc[j][1] + puA + cv1 + s0v);
            S[r0 + 8][c0]     = fast_exp(acc[j][2] + puB + cv0 + s0v);
            S[r0 + 8][c0 + 1] = fast_exp(acc[j][3] + puB + cv1 + s0v);
        }
    }

    // ---- epilogue prefetch: independent global loads, consumed 2 syncs later
    float4 pv[4], cw4[4];
    #pragma unroll
    for (int r = 0; r < 4; r++) {
        const int row = w * 4 + r;
        pv[r]  = *(const float4*)&pepG[(size_t)row * HDIM + 4 * l];
        cw4[r] = *(const float4*)&cdrG[(size_t)row * HDIM + 4 * l];
    }
    __syncthreads();

    // ---- row/col sums: 16 warps x 8 tasks, lane-parallel + shfl reduce ----
    #pragma unroll
    for (int q = 0; q < 8; q++) {
        const int task = w + q * 16;      // 0..127
        float s;
        if (task < 64) {                  // row sum
            s = S[task][l] + S[task][l + 32];
        } else {                          // col sum (stride 65 -> conflict-free)
            const int c = task - 64;
            s = S[l][c] + S[l + 32][c];
        }
        #pragma unroll
        for (int o = 16; o > 0; o >>= 1) s += __shfl_xor_sync(~0u, s, o);
        if (l == 0) {
            if (task < 64) sm.RS[task] = s;
            else           sm.CS[task - 64] = s;
        }
    }
    __syncthreads();
    if (t < 32) {
        float z = sm.RS[t] + sm.RS[t + 32];
        #pragma unroll
        for (int o = 16; o > 0; o >>= 1) z += __shfl_xor_sync(~0u, z, o);
        if (t == 0) sm.Z = z;
    }
    __syncthreads();

    // ---- epilogue (fp32, prefetched registers) ----
    {
        float a0 = 0.f, a1 = 0.f, a2 = 0.f, a3 = 0.f;
        #pragma unroll
        for (int r = 0; r < 4; r++) {
            const int row = w * 4 + r;
            const float cw = sm.CS[row];
            const float rw = sm.RS[row];
            a0 += pv[r].x * cw + cw4[r].x * rw;
            a1 += pv[r].y * cw + cw4[r].y * rw;
            a2 += pv[r].z * cw + cw4[r].z * rw;
            a3 += pv[r].w * cw + cw4[r].w * rw;
        }
        *(float4*)&sm.EP[w][4 * l] = make_float4(a0, a1, a2, a3);
    }
    __syncthreads();
    if (t < HDIM) {
        float s = 0.f;
        #pragma unroll
        for (int i = 0; i < 16; i++) s += sm.EP[i][t];
        out[(size_t)b * HDIM + t] = s / sm.Z;
    }
}

// ---------------------------------------------------------------------------
extern "C" void kernel_launch(void* const* d_in, const int* in_sizes, int n_in,
                              void* d_out, int out_size) {
    const float* pep = (const float*)d_in[0];
    const float* cdr = (const float*)d_in[1];
    const float* Wc  = (const float*)d_in[2];
    const float* bc  = (const float*)d_in[3];
    const float* Wp  = (const float*)d_in[4];
    const float* bp  = (const float*)d_in[5];
    float* out = (float*)d_out;

    const int B = in_sizes[0] / (LSEQ * HDIM);   // 256

    cudaFuncSetAttribute(main_kernel, cudaFuncAttributeMaxDynamicSharedMemorySize,
                         (int)sizeof(SmemMain));

    pre_mm<<<40, 256>>>(Wp, Wc, bp, bc);
    main_kernel<<<B, 512, sizeof(SmemMain)>>>(pep, cdr, out);
}